// round 6
// baseline (speedup 1.0000x reference)
#include <cuda_runtime.h>
#include <math.h>
#include <stdint.h>

// Problem constants (fixed by the dataset)
#define NS   20000      // source nodes
#define NT   20000      // target nodes
#define EE   100000     // edges per type
#define FF   128        // input features
#define HCC  256        // H*C
#define TT   6          // edge types
#define NEG_SLOPE 0.2f

// ---------------- scratch (static device globals; no allocation) -------------
__device__ __align__(16) float g_hs1 [(size_t)NS*HCC];
__device__ __align__(16) float g_hd1 [(size_t)NT*HCC];
__device__ __align__(16) float g_h1  [(size_t)NT*HCC];   // layer-1 aggregated (pre-relu)
__device__ __align__(16) float g_hs2 [(size_t)NS*HCC];
__device__ __align__(16) float g_hd2 [(size_t)NT*HCC];
__device__ __align__(16) float g_out2[(size_t)NT*HCC];   // layer-2 aggregated
__device__ __align__(16) float g_escore[(size_t)EE*4];
__device__ __align__(16) float g_wbuf  [(size_t)EE*4];
__device__ unsigned g_emax1[NT*4];
__device__ unsigned g_emax2[NT*4];
__device__ float    g_denom1[NT*4];
__device__ float    g_denom2[NT*4];
__device__ float    g_pooled[HCC];
__device__ float    g_agg[8];

// monotone float <-> uint encoding for atomicMax on floats
__device__ __forceinline__ unsigned fenc(float f) {
    unsigned u = __float_as_uint(f);
    return u ^ ((unsigned)((int)u >> 31) | 0x80000000u);
}
__device__ __forceinline__ float fdec(unsigned u) {
    unsigned b = (u & 0x80000000u) ? (u ^ 0x80000000u) : ~u;
    return __uint_as_float(b);
}
#define ENC_NEG_INF 0x007FFFFFu   // fenc(-inf)

// ---------------- init: zero accumulators, set segment-max identity ----------
__global__ void init_kernel() {
    size_t stride = (size_t)gridDim.x * blockDim.x;
    size_t i0 = (size_t)blockIdx.x * blockDim.x + threadIdx.x;
    for (size_t i = i0; i < (size_t)NT * HCC; i += stride) { g_h1[i] = 0.f; g_out2[i] = 0.f; }
    for (size_t i = i0; i < (size_t)NT * 4; i += stride) {
        g_denom1[i] = 0.f; g_denom2[i] = 0.f;
        g_emax1[i] = ENC_NEG_INF; g_emax2[i] = ENC_NEG_INF;
    }
    if (i0 < HCC) g_pooled[i0] = 0.f;
    if (i0 < 8)   g_agg[i0] = 0.f;
}

// ---------------- SGEMM: C[M,256] = op(A[M,K]) @ B[K,256] --------------------
// MASK_A: multiply row r of A by mask[r].  RELU_A: relu on A elements.
// Block = 256 threads, tile 64(M) x 64(N) x 16(K), 4x4 microtile.
// Inner-loop smem loads vectorized to LDS.128 (rows are 272B => 16B-aligned).
template<int MASK_A, int RELU_A>
__global__ void sgemm256(const float* __restrict__ A, const float* __restrict__ B,
                         float* __restrict__ C, const float* __restrict__ mask,
                         int M, int K)
{
    __shared__ __align__(16) float As[16][68];
    __shared__ __align__(16) float Bs[16][68];
    const int tid = threadIdx.x;              // 256 threads
    const int bm = blockIdx.y * 64;
    const int bn = blockIdx.x * 64;
    const int tm = (tid >> 4) << 2;           // 0..60, multiple of 4
    const int tn = (tid & 15) << 2;           // 0..60, multiple of 4
    const int arow = tid >> 2;                // 0..63
    const int acol = (tid & 3) << 2;          // 0,4,8,12
    const int brow = tid >> 4;                // 0..15
    const int bcol = (tid & 15) << 2;         // 0..60

    float acc[4][4];
#pragma unroll
    for (int i = 0; i < 4; i++)
#pragma unroll
        for (int j = 0; j < 4; j++) acc[i][j] = 0.f;

    const int grow = bm + arow;
    const bool avalid = grow < M;
    float mval = 1.f;
    if (MASK_A) mval = avalid ? __ldg(mask + grow) : 0.f;
    const float* Arow = A + (size_t)grow * K;

    for (int k0 = 0; k0 < K; k0 += 16) {
        float4 av = avalid ? *(const float4*)(Arow + k0 + acol)
                           : make_float4(0.f, 0.f, 0.f, 0.f);
        if (MASK_A) { av.x *= mval; av.y *= mval; av.z *= mval; av.w *= mval; }
        if (RELU_A) {
            av.x = fmaxf(av.x, 0.f); av.y = fmaxf(av.y, 0.f);
            av.z = fmaxf(av.z, 0.f); av.w = fmaxf(av.w, 0.f);
        }
        As[acol + 0][arow] = av.x; As[acol + 1][arow] = av.y;
        As[acol + 2][arow] = av.z; As[acol + 3][arow] = av.w;

        float4 bv = *(const float4*)(B + (size_t)(k0 + brow) * HCC + bn + bcol);
        *(float4*)&Bs[brow][bcol] = bv;
        __syncthreads();

#pragma unroll
        for (int k = 0; k < 16; k++) {
            const float4 a4 = *(const float4*)&As[k][tm];   // LDS.128
            const float4 b4 = *(const float4*)&Bs[k][tn];   // LDS.128
            acc[0][0] = fmaf(a4.x, b4.x, acc[0][0]); acc[0][1] = fmaf(a4.x, b4.y, acc[0][1]);
            acc[0][2] = fmaf(a4.x, b4.z, acc[0][2]); acc[0][3] = fmaf(a4.x, b4.w, acc[0][3]);
            acc[1][0] = fmaf(a4.y, b4.x, acc[1][0]); acc[1][1] = fmaf(a4.y, b4.y, acc[1][1]);
            acc[1][2] = fmaf(a4.y, b4.z, acc[1][2]); acc[1][3] = fmaf(a4.y, b4.w, acc[1][3]);
            acc[2][0] = fmaf(a4.z, b4.x, acc[2][0]); acc[2][1] = fmaf(a4.z, b4.y, acc[2][1]);
            acc[2][2] = fmaf(a4.z, b4.z, acc[2][2]); acc[2][3] = fmaf(a4.z, b4.w, acc[2][3]);
            acc[3][0] = fmaf(a4.w, b4.x, acc[3][0]); acc[3][1] = fmaf(a4.w, b4.y, acc[3][1]);
            acc[3][2] = fmaf(a4.w, b4.z, acc[3][2]); acc[3][3] = fmaf(a4.w, b4.w, acc[3][3]);
        }
        __syncthreads();
    }

#pragma unroll
    for (int i = 0; i < 4; i++) {
        int r = bm + tm + i;
        if (r < M) {
            float4 v = make_float4(acc[i][0], acc[i][1], acc[i][2], acc[i][3]);
            *(float4*)(C + (size_t)r * HCC + bn + tn) = v;
        }
    }
}

// ---------------- edge pass 1: GATv2 scores + segment max --------------------
// one warp per edge; lane l handles 8 channels, head = l/8 (4 heads x 8 lanes).
__global__ void edge_score_max(const int* __restrict__ src, const int* __restrict__ dst,
                               const float* __restrict__ hs, const float* __restrict__ hd,
                               const float* __restrict__ avec,
                               float* __restrict__ escore, unsigned* __restrict__ emax)
{
    int gw = (int)((blockIdx.x * (size_t)blockDim.x + threadIdx.x) >> 5);
    if (gw >= EE) return;
    int lane = threadIdx.x & 31;
    int s = __ldg(src + gw), d = __ldg(dst + gw);
    const float4* ps = (const float4*)(hs + (size_t)s * HCC);
    const float4* pd = (const float4*)(hd + (size_t)d * HCC);
    const float4* pa = (const float4*)avec;
    float sum = 0.f;
#pragma unroll
    for (int q = 0; q < 2; q++) {
        int idx = lane * 2 + q;
        float4 va = __ldg(pa + idx);
        float4 vs = ps[idx];
        float4 vd = pd[idx];
        float z;
        z = vs.x + vd.x; z = z > 0.f ? z : NEG_SLOPE * z; sum = fmaf(z, va.x, sum);
        z = vs.y + vd.y; z = z > 0.f ? z : NEG_SLOPE * z; sum = fmaf(z, va.y, sum);
        z = vs.z + vd.z; z = z > 0.f ? z : NEG_SLOPE * z; sum = fmaf(z, va.z, sum);
        z = vs.w + vd.w; z = z > 0.f ? z : NEG_SLOPE * z; sum = fmaf(z, va.w, sum);
    }
    // reduce 8 lanes within each head (lanes [8h, 8h+8))
    sum += __shfl_down_sync(0xffffffffu, sum, 4, 8);
    sum += __shfl_down_sync(0xffffffffu, sum, 2, 8);
    sum += __shfl_down_sync(0xffffffffu, sum, 1, 8);
    if ((lane & 7) == 0) {
        int h = lane >> 3;
        escore[(size_t)gw * 4 + h] = sum;
        atomicMax(&emax[(size_t)d * 4 + h], fenc(sum));
    }
}

// ---------------- edge pass 2: exp(e - max) * mask, segment denom ------------
__global__ void edge_softmax_denom(const int* __restrict__ dst,
                                   const float* __restrict__ escore,
                                   const unsigned* __restrict__ emax,
                                   const float* __restrict__ emask,
                                   float* __restrict__ w, float* __restrict__ denom)
{
    int e = blockIdx.x * blockDim.x + threadIdx.x;
    if (e >= EE) return;
    int d = __ldg(dst + e);
    float m = __ldg(emask + e);
#pragma unroll
    for (int h = 0; h < 4; h++) {
        float mx = fdec(emax[(size_t)d * 4 + h]);
        float ww = expf(escore[(size_t)e * 4 + h] - mx) * m;
        w[(size_t)e * 4 + h] = ww;
        atomicAdd(&denom[(size_t)d * 4 + h], ww);
    }
}

// ---------------- edge pass 3: out[dst] += alpha * hs[src] -------------------
__global__ void edge_aggregate(const int* __restrict__ src, const int* __restrict__ dst,
                               const float* __restrict__ hs, const float* __restrict__ w,
                               const float* __restrict__ denom, float* __restrict__ out)
{
    int gw = (int)((blockIdx.x * (size_t)blockDim.x + threadIdx.x) >> 5);
    if (gw >= EE) return;
    int lane = threadIdx.x & 31;
    int s = __ldg(src + gw), d = __ldg(dst + gw);
    float alpha = 0.f;
    if ((lane & 7) == 0) {
        int h = lane >> 3;
        alpha = w[(size_t)gw * 4 + h] / (denom[(size_t)d * 4 + h] + 1e-16f);
    }
    alpha = __shfl_sync(0xffffffffu, alpha, lane & 24);   // broadcast head leader
    const float4* ps = (const float4*)(hs + (size_t)s * HCC);
    float* po = out + (size_t)d * HCC;
#pragma unroll
    for (int q = 0; q < 2; q++) {
        int idx = lane * 2 + q;
        float4 v = ps[idx];
        asm volatile("red.global.add.v4.f32 [%0], {%1,%2,%3,%4};"
                     :: "l"(po + idx * 4),
                        "f"(alpha * v.x), "f"(alpha * v.y),
                        "f"(alpha * v.z), "f"(alpha * v.w)
                     : "memory");
    }
}

// ---------------- mean-pool over nodes (column sums) -------------------------
__global__ void pool_kernel(const float* __restrict__ x, float* __restrict__ pooled)
{
    float s = 0.f;
    for (int r = blockIdx.x; r < NT; r += gridDim.x)
        s += x[(size_t)r * HCC + threadIdx.x];
    atomicAdd(&pooled[threadIdx.x], s);
}

// ---------------- edge_attr per-type means -----------------------------------
__global__ void edge_attr_agg(const float* __restrict__ ea, float* __restrict__ agg)
{
    int t = blockIdx.y;
    const float* p = ea + (size_t)t * EE;
    float s = 0.f;
    for (int i = blockIdx.x * blockDim.x + threadIdx.x; i < EE; i += gridDim.x * blockDim.x)
        s += p[i];
    __shared__ float sm[256];
    sm[threadIdx.x] = s;
    __syncthreads();
    for (int o = 128; o > 0; o >>= 1) {
        if (threadIdx.x < o) sm[threadIdx.x] += sm[threadIdx.x + o];
        __syncthreads();
    }
    if (threadIdx.x == 0) atomicAdd(&agg[t], sm[0]);
}

// ---------------- classifier head --------------------------------------------
__global__ void finalize_kernel(const float* __restrict__ Wc, const float* __restrict__ bc,
                                float* __restrict__ out)
{
    __shared__ float sm[256];
    int t = threadIdx.x;
    sm[t] = g_pooled[t] * (1.0f / NT) * Wc[t];
    __syncthreads();
    for (int o = 128; o > 0; o >>= 1) {
        if (t < o) sm[t] += sm[t + o];
        __syncthreads();
    }
    if (t == 0) {
        float s = sm[0];
#pragma unroll
        for (int k = 0; k < TT; k++) s += g_agg[k] * (1.0f / EE) * Wc[HCC + k];
        s += bc[0];
        out[0] = 1.f / (1.f + expf(-s));
    }
}

// ---------------- host orchestration -----------------------------------------
extern "C" void kernel_launch(void* const* d_in, const int* in_sizes, int n_in,
                              void* d_out, int out_size)
{
    (void)in_sizes; (void)n_in; (void)out_size;
    const float* xs    = (const float*)d_in[0];
    const float* xt5   = (const float*)d_in[1] + (size_t)(TT - 1) * NT * FF;
    const float* ea    = (const float*)d_in[2];
    const float* nmask = (const float*)d_in[3];
    const float* emask = (const float*)d_in[4];
    const int*   ei    = (const int*)d_in[5];
    const int*   src5  = ei + (size_t)(TT - 1) * 2 * EE;
    const int*   dst5  = src5 + EE;
    const float* W1s5  = (const float*)d_in[6]  + (size_t)(TT - 1) * FF * HCC;
    const float* W1d5  = (const float*)d_in[7]  + (size_t)(TT - 1) * FF * HCC;
    const float* a1_5  = (const float*)d_in[8]  + (size_t)(TT - 1) * HCC;
    const float* W2s5  = (const float*)d_in[9]  + (size_t)(TT - 1) * FF * HCC;
    const float* W2d5  = (const float*)d_in[10] + (size_t)(TT - 1) * HCC * HCC;
    const float* a2_5  = (const float*)d_in[11] + (size_t)(TT - 1) * HCC;
    const float* Wc    = (const float*)d_in[12];
    const float* bc    = (const float*)d_in[13];
    float* out = (float*)d_out;

    float *hs1, *hd1, *h1, *hs2, *hd2, *out2, *esc, *wb, *den1, *den2, *pooled, *agg;
    unsigned *emx1, *emx2;
    cudaGetSymbolAddress((void**)&hs1,    g_hs1);
    cudaGetSymbolAddress((void**)&hd1,    g_hd1);
    cudaGetSymbolAddress((void**)&h1,     g_h1);
    cudaGetSymbolAddress((void**)&hs2,    g_hs2);
    cudaGetSymbolAddress((void**)&hd2,    g_hd2);
    cudaGetSymbolAddress((void**)&out2,   g_out2);
    cudaGetSymbolAddress((void**)&esc,    g_escore);
    cudaGetSymbolAddress((void**)&wb,     g_wbuf);
    cudaGetSymbolAddress((void**)&den1,   g_denom1);
    cudaGetSymbolAddress((void**)&den2,   g_denom2);
    cudaGetSymbolAddress((void**)&emx1,   g_emax1);
    cudaGetSymbolAddress((void**)&emx2,   g_emax2);
    cudaGetSymbolAddress((void**)&pooled, g_pooled);
    cudaGetSymbolAddress((void**)&agg,    g_agg);

    dim3 gemm_grid(HCC / 64, (NT + 63) / 64);
    const int EW_BLOCKS = (int)(((size_t)EE * 32 + 255) / 256);  // warp-per-edge kernels
    const int E_BLOCKS  = (EE + 255) / 256;

    init_kernel<<<1024, 256>>>();

    // layer-1 projections + layer-2 source projection (independent of layer 1)
    sgemm256<1, 0><<<gemm_grid, 256>>>(xs,  W1s5, hs1, nmask, NS, FF);
    sgemm256<1, 0><<<gemm_grid, 256>>>(xt5, W1d5, hd1, nmask, NT, FF);
    sgemm256<1, 0><<<gemm_grid, 256>>>(xs,  W2s5, hs2, nmask, NS, FF);

    // layer-1 attention
    edge_score_max<<<EW_BLOCKS, 256>>>(src5, dst5, hs1, hd1, a1_5, esc, emx1);
    edge_softmax_denom<<<E_BLOCKS, 256>>>(dst5, esc, emx1, emask, wb, den1);
    edge_aggregate<<<EW_BLOCKS, 256>>>(src5, dst5, hs1, wb, den1, h1);

    // layer-2 target projection: relu(h1) @ W2_dst  (relu folded into A-load)
    sgemm256<0, 1><<<gemm_grid, 256>>>(h1, W2d5, hd2, nullptr, NT, HCC);

    // layer-2 attention
    edge_score_max<<<EW_BLOCKS, 256>>>(src5, dst5, hs2, hd2, a2_5, esc, emx2);
    edge_softmax_denom<<<E_BLOCKS, 256>>>(dst5, esc, emx2, emask, wb, den2);
    edge_aggregate<<<EW_BLOCKS, 256>>>(src5, dst5, hs2, wb, den2, out2);

    // head
    pool_kernel<<<128, 256>>>(out2, pooled);
    edge_attr_agg<<<dim3(32, TT), 256>>>(ea, agg);
    finalize_kernel<<<1, 256>>>(Wc, bc, out);
}